// round 5
// baseline (speedup 1.0000x reference)
#include <cuda_runtime.h>

// ShortConvolution: depthwise causal conv1d
// x: (B=4, L=4096, D=2048) f32, w: (K=4, 1, D) f32, b: (D,) f32 -> y: (B,L,D) f32
// y[b,l,d] = sum_{k=0..3} w[k,d] * x[b, l-3+k, d] + b[d]

constexpr int B_ = 4;
constexpr int L_ = 4096;
constexpr int D_ = 2048;
constexpr int K_ = 4;
constexpr int D4 = D_ / 4;      // 512 float4 lanes
constexpr int L_TILE = 16;
constexpr int TPB = 256;        // threads per block (d4 lanes)

__global__ __launch_bounds__(TPB)
void ShortConvolution_137438953679_kernel(
    const float4* __restrict__ x,
    const float*  __restrict__ w,
    const float*  __restrict__ bias,
    float4*       __restrict__ y)
{
    const int d4 = blockIdx.x * TPB + threadIdx.x;   // 0..511
    const int l0 = blockIdx.y * L_TILE;              // start L of tile
    const int b  = blockIdx.z;

    // Per-channel weights (K=4) and bias, held in registers.
    const float4* w4 = reinterpret_cast<const float4*>(w);
    const float4 w0 = __ldg(&w4[0 * D4 + d4]);
    const float4 w1 = __ldg(&w4[1 * D4 + d4]);
    const float4 w2 = __ldg(&w4[2 * D4 + d4]);
    const float4 w3 = __ldg(&w4[3 * D4 + d4]);
    const float4 bb = __ldg(&reinterpret_cast<const float4*>(bias)[d4]);

    const size_t base = (size_t)b * L_ * D4 + (size_t)l0 * D4 + d4;
    const float4* xp = x + base;
    float4*       yp = y + base;

    // Rolling window: xm3 = x[l-3], xm2 = x[l-2], xm1 = x[l-1]
    float4 xm3, xm2, xm1;
    const float4 z4 = make_float4(0.f, 0.f, 0.f, 0.f);
    if (l0 == 0) {
        xm3 = z4; xm2 = z4; xm1 = z4;
    } else {
        xm3 = xp[-3 * D4];
        xm2 = xp[-2 * D4];
        xm1 = xp[-1 * D4];
    }

    #pragma unroll
    for (int j = 0; j < L_TILE; ++j) {
        const float4 xc = xp[(size_t)j * D4];
        float4 o;
        o.x = fmaf(w0.x, xm3.x, fmaf(w1.x, xm2.x, fmaf(w2.x, xm1.x, fmaf(w3.x, xc.x, bb.x))));
        o.y = fmaf(w0.y, xm3.y, fmaf(w1.y, xm2.y, fmaf(w2.y, xm1.y, fmaf(w3.y, xc.y, bb.y))));
        o.z = fmaf(w0.z, xm3.z, fmaf(w1.z, xm2.z, fmaf(w2.z, xm1.z, fmaf(w3.z, xc.z, bb.z))));
        o.w = fmaf(w0.w, xm3.w, fmaf(w1.w, xm2.w, fmaf(w2.w, xm1.w, fmaf(w3.w, xc.w, bb.w))));
        yp[(size_t)j * D4] = o;
        xm3 = xm2; xm2 = xm1; xm1 = xc;
    }
}

extern "C" void kernel_launch(void* const* d_in, const int* in_sizes, int n_in,
                              void* d_out, int out_size)
{
    const float* x = (const float*)d_in[0];   // (B, L, D)
    const float* w = (const float*)d_in[1];   // (K, 1, D)
    const float* b = (const float*)d_in[2];   // (D,)
    float* y = (float*)d_out;

    dim3 grid(D4 / TPB, L_ / L_TILE, B_);     // (2, 256, 4)
    dim3 block(TPB);
    ShortConvolution_137438953679_kernel<<<grid, block>>>(
        reinterpret_cast<const float4*>(x), w, b,
        reinterpret_cast<float4*>(y));
}